// round 1
// baseline (speedup 1.0000x reference)
#include <cuda_runtime.h>
#include <cuda_bf16.h>
#include <math.h>

// Problem constants
#define N_NODES 100000
#define E_EDGES 1600000
#define C_DIM 256
#define H_DIM 128
#define F_DIM 64

// Scratch (allocation-free rule: __device__ globals)
__device__ float g_buf1[N_NODES * H_DIM];   // 51.2 MB
__device__ float g_buf2[N_NODES * H_DIM];   // 51.2 MB
__device__ int   g_rowptr[N_NODES + 1];

// ---------------------------------------------------------------------------
// Row-pointer build: lower_bound over sorted edge_row
// ---------------------------------------------------------------------------
__global__ void rowptr_kernel(const int* __restrict__ edge_row) {
    int i = blockIdx.x * blockDim.x + threadIdx.x;
    if (i > N_NODES) return;
    int lo = 0, hi = E_EDGES;
    while (lo < hi) {
        int mid = (lo + hi) >> 1;
        if (edge_row[mid] < i) lo = mid + 1;
        else hi = mid;
    }
    g_rowptr[i] = lo;
}

// ---------------------------------------------------------------------------
// GEMM: out[m][n] = sum_k A[m][k] * W[n][k]   (A: [M,K] row-major, W: [BN,K])
// BM=128, BK=32, 256 threads, per-thread TM x TN = 8 x (BN/16)
// ---------------------------------------------------------------------------
template<int BN, int TN, int K>
__global__ void __launch_bounds__(256) gemm_nt(const float* __restrict__ A,
                                               const float* __restrict__ W,
                                               float* __restrict__ out,
                                               int M) {
    constexpr int BM = 128;
    constexpr int BK = 32;
    constexpr int TM = 8;
    constexpr int PAD = 4;            // keep 16B alignment for float4 LDS
    __shared__ float As[BK][BM + PAD];
    __shared__ float Bs[BK][BN + PAD];

    const int tid  = threadIdx.x;
    const int bm   = blockIdx.x * BM;
    const int tcol = tid % (BN / TN);   // 16 columns of threads
    const int trow = tid / (BN / TN);   // 16 rows of threads

    float acc[TM][TN];
#pragma unroll
    for (int i = 0; i < TM; i++)
#pragma unroll
        for (int j = 0; j < TN; j++) acc[i][j] = 0.f;

    for (int k0 = 0; k0 < K; k0 += BK) {
        // Load A tile (transposed to As[k][m]) with float4 global reads
#pragma unroll
        for (int idx = tid; idx < BM * (BK / 4); idx += 256) {
            int m  = idx / (BK / 4);
            int kv = idx % (BK / 4);
            int row = bm + m;
            float4 a = make_float4(0.f, 0.f, 0.f, 0.f);
            if (row < M)
                a = *reinterpret_cast<const float4*>(&A[(size_t)row * K + k0 + kv * 4]);
            As[kv * 4 + 0][m] = a.x;
            As[kv * 4 + 1][m] = a.y;
            As[kv * 4 + 2][m] = a.z;
            As[kv * 4 + 3][m] = a.w;
        }
        // Load W tile (transposed to Bs[k][n]); W has exactly BN rows
#pragma unroll
        for (int idx = tid; idx < BN * (BK / 4); idx += 256) {
            int n  = idx / (BK / 4);
            int kv = idx % (BK / 4);
            float4 b = *reinterpret_cast<const float4*>(&W[(size_t)n * K + k0 + kv * 4]);
            Bs[kv * 4 + 0][n] = b.x;
            Bs[kv * 4 + 1][n] = b.y;
            Bs[kv * 4 + 2][n] = b.z;
            Bs[kv * 4 + 3][n] = b.w;
        }
        __syncthreads();

#pragma unroll
        for (int kk = 0; kk < BK; kk++) {
            float a_frag[TM];
            float b_frag[TN];
#pragma unroll
            for (int i4 = 0; i4 < TM / 4; i4++) {
                float4 a = *reinterpret_cast<const float4*>(&As[kk][trow * TM + i4 * 4]);
                a_frag[i4 * 4 + 0] = a.x;
                a_frag[i4 * 4 + 1] = a.y;
                a_frag[i4 * 4 + 2] = a.z;
                a_frag[i4 * 4 + 3] = a.w;
            }
#pragma unroll
            for (int j4 = 0; j4 < TN / 4; j4++) {
                float4 b = *reinterpret_cast<const float4*>(&Bs[kk][tcol * TN + j4 * 4]);
                b_frag[j4 * 4 + 0] = b.x;
                b_frag[j4 * 4 + 1] = b.y;
                b_frag[j4 * 4 + 2] = b.z;
                b_frag[j4 * 4 + 3] = b.w;
            }
#pragma unroll
            for (int i = 0; i < TM; i++)
#pragma unroll
                for (int j = 0; j < TN; j++)
                    acc[i][j] = fmaf(a_frag[i], b_frag[j], acc[i][j]);
        }
        __syncthreads();
    }

    // Store
#pragma unroll
    for (int i = 0; i < TM; i++) {
        int row = bm + trow * TM + i;
        if (row < M) {
#pragma unroll
            for (int j4 = 0; j4 < TN / 4; j4++) {
                float4 v = make_float4(acc[i][j4 * 4 + 0], acc[i][j4 * 4 + 1],
                                       acc[i][j4 * 4 + 2], acc[i][j4 * 4 + 3]);
                *reinterpret_cast<float4*>(&out[(size_t)row * BN + tcol * TN + j4 * 4]) = v;
            }
        }
    }
}

// ---------------------------------------------------------------------------
// SpMM (H=128): one warp per row, float4 per lane, optional ReLU
// ---------------------------------------------------------------------------
template<bool RELU>
__global__ void __launch_bounds__(256) spmm128_kernel(const int* __restrict__ edge_col,
                                                      const float* __restrict__ edge_val,
                                                      const float* __restrict__ Z,
                                                      float* __restrict__ out) {
    int gw   = (blockIdx.x * blockDim.x + threadIdx.x) >> 5;
    int lane = threadIdx.x & 31;
    if (gw >= N_NODES) return;
    int s = g_rowptr[gw];
    int e = g_rowptr[gw + 1];

    float4 acc = make_float4(0.f, 0.f, 0.f, 0.f);
    for (int i = s; i < e; i++) {
        int   col = __ldg(&edge_col[i]);
        float val = __ldg(&edge_val[i]);
        float4 z = *reinterpret_cast<const float4*>(&Z[(size_t)col * H_DIM + lane * 4]);
        acc.x = fmaf(val, z.x, acc.x);
        acc.y = fmaf(val, z.y, acc.y);
        acc.z = fmaf(val, z.z, acc.z);
        acc.w = fmaf(val, z.w, acc.w);
    }
    if (RELU) {
        acc.x = fmaxf(acc.x, 0.f);
        acc.y = fmaxf(acc.y, 0.f);
        acc.z = fmaxf(acc.z, 0.f);
        acc.w = fmaxf(acc.w, 0.f);
    }
    *reinterpret_cast<float4*>(&out[(size_t)gw * H_DIM + lane * 4]) = acc;
}

// ---------------------------------------------------------------------------
// Final SpMM (F=64) fused with row softmax: one warp per row, float2 per lane
// ---------------------------------------------------------------------------
__global__ void __launch_bounds__(256) spmm64_softmax_kernel(const int* __restrict__ edge_col,
                                                             const float* __restrict__ edge_val,
                                                             const float* __restrict__ Z,
                                                             float* __restrict__ out) {
    int gw   = (blockIdx.x * blockDim.x + threadIdx.x) >> 5;
    int lane = threadIdx.x & 31;
    if (gw >= N_NODES) return;
    int s = g_rowptr[gw];
    int e = g_rowptr[gw + 1];

    float a0 = 0.f, a1 = 0.f;
    for (int i = s; i < e; i++) {
        int   col = __ldg(&edge_col[i]);
        float val = __ldg(&edge_val[i]);
        float2 z = *reinterpret_cast<const float2*>(&Z[(size_t)col * F_DIM + lane * 2]);
        a0 = fmaf(val, z.x, a0);
        a1 = fmaf(val, z.y, a1);
    }
    // warp softmax over the 64 values (2 per lane)
    float m = fmaxf(a0, a1);
#pragma unroll
    for (int off = 16; off > 0; off >>= 1)
        m = fmaxf(m, __shfl_xor_sync(0xFFFFFFFFu, m, off));
    float e0 = expf(a0 - m);
    float e1 = expf(a1 - m);
    float ssum = e0 + e1;
#pragma unroll
    for (int off = 16; off > 0; off >>= 1)
        ssum += __shfl_xor_sync(0xFFFFFFFFu, ssum, off);
    float inv = 1.0f / ssum;
    float2 r = make_float2(e0 * inv, e1 * inv);
    *reinterpret_cast<float2*>(&out[(size_t)gw * F_DIM + lane * 2]) = r;
}

// ---------------------------------------------------------------------------
// Launch
// ---------------------------------------------------------------------------
extern "C" void kernel_launch(void* const* d_in, const int* in_sizes, int n_in,
                              void* d_out, int out_size) {
    const float* X        = (const float*)d_in[0];
    const int*   edge_row = (const int*)d_in[1];
    const int*   edge_col = (const int*)d_in[2];
    const float* edge_val = (const float*)d_in[3];
    const float* W0       = (const float*)d_in[4];
    const float* Wh0      = (const float*)d_in[5];
    const float* W1       = (const float*)d_in[6];
    float*       out      = (float*)d_out;

    float *buf1, *buf2;
    cudaGetSymbolAddress((void**)&buf1, g_buf1);
    cudaGetSymbolAddress((void**)&buf2, g_buf2);

    const int gemm_grid = (N_NODES + 127) / 128;               // 782
    const int spmm_grid = (N_NODES * 32 + 255) / 256;          // 12500

    // row pointers (edge_row sorted)
    rowptr_kernel<<<(N_NODES + 1 + 255) / 256, 256>>>(edge_row);

    // Layer 0: buf1 = X @ W0^T ; buf2 = relu(A @ buf1)
    gemm_nt<128, 8, 256><<<gemm_grid, 256>>>(X, W0, buf1, N_NODES);
    spmm128_kernel<true><<<spmm_grid, 256>>>(edge_col, edge_val, buf1, buf2);

    // Hidden: buf1 = buf2 @ Wh0^T ; buf2 = relu(A @ buf1)
    gemm_nt<128, 8, 128><<<gemm_grid, 256>>>(buf2, Wh0, buf1, N_NODES);
    spmm128_kernel<true><<<spmm_grid, 256>>>(edge_col, edge_val, buf1, buf2);

    // Output: buf1 = buf2 @ W1^T ; out = softmax(A @ buf1)
    gemm_nt<64, 4, 128><<<gemm_grid, 256>>>(buf2, W1, buf1, N_NODES);
    spmm64_softmax_kernel<<<spmm_grid, 256>>>(edge_col, edge_val, buf1, out);
}

// round 3
// speedup vs baseline: 1.5447x; 1.5447x over previous
#include <cuda_runtime.h>
#include <cuda_bf16.h>
#include <math.h>
#include <stdint.h>

// Problem constants
#define N_NODES 100000
#define E_EDGES 1600000
#define C_DIM 256
#define H_DIM 128
#define F_DIM 64

// Scratch (allocation-free rule: __device__ globals)
__device__ float g_buf1[N_NODES * H_DIM];   // 51.2 MB
__device__ float g_buf2[N_NODES * H_DIM];   // 51.2 MB
__device__ int   g_rowptr[N_NODES + 1];

// ---------------------------------------------------------------------------
// Helpers
// ---------------------------------------------------------------------------
__device__ __forceinline__ uint32_t smem_u32(const void* p) {
    uint32_t a;
    asm("{ .reg .u64 t; cvta.to.shared.u64 t, %1; cvt.u32.u64 %0, t; }" : "=r"(a) : "l"(p));
    return a;
}

__device__ __forceinline__ void ldsm_x4(uint32_t (&r)[4], uint32_t addr) {
    asm volatile("ldmatrix.sync.aligned.m8n8.x4.shared.b16 {%0,%1,%2,%3}, [%4];"
                 : "=r"(r[0]), "=r"(r[1]), "=r"(r[2]), "=r"(r[3]) : "r"(addr));
}

__device__ __forceinline__ void mma_bf16(float (&d)[4], const uint32_t (&a)[4],
                                         uint32_t b0, uint32_t b1) {
    asm volatile(
        "mma.sync.aligned.m16n8k16.row.col.f32.bf16.bf16.f32 "
        "{%0,%1,%2,%3}, {%4,%5,%6,%7}, {%8,%9}, {%0,%1,%2,%3};"
        : "+f"(d[0]), "+f"(d[1]), "+f"(d[2]), "+f"(d[3])
        : "r"(a[0]), "r"(a[1]), "r"(a[2]), "r"(a[3]), "r"(b0), "r"(b1));
}

// float4 -> (hi bf16x2 pair, lo bf16x2 pair)
__device__ __forceinline__ void split4(float4 v, uint2& hv, uint2& lv) {
    __nv_bfloat16 h0 = __float2bfloat16(v.x);
    __nv_bfloat16 h1 = __float2bfloat16(v.y);
    __nv_bfloat16 h2 = __float2bfloat16(v.z);
    __nv_bfloat16 h3 = __float2bfloat16(v.w);
    __nv_bfloat16 l0 = __float2bfloat16(v.x - __bfloat162float(h0));
    __nv_bfloat16 l1 = __float2bfloat16(v.y - __bfloat162float(h1));
    __nv_bfloat16 l2 = __float2bfloat16(v.z - __bfloat162float(h2));
    __nv_bfloat16 l3 = __float2bfloat16(v.w - __bfloat162float(h3));
    __nv_bfloat162 hp0(h0, h1), hp1(h2, h3), lp0(l0, l1), lp1(l2, l3);
    hv = make_uint2(*reinterpret_cast<uint32_t*>(&hp0), *reinterpret_cast<uint32_t*>(&hp1));
    lv = make_uint2(*reinterpret_cast<uint32_t*>(&lp0), *reinterpret_cast<uint32_t*>(&lp1));
}

// ---------------------------------------------------------------------------
// Row-pointer build: lower_bound over sorted edge_row
// ---------------------------------------------------------------------------
__global__ void rowptr_kernel(const int* __restrict__ edge_row) {
    int i = blockIdx.x * blockDim.x + threadIdx.x;
    if (i > N_NODES) return;
    int lo = 0, hi = E_EDGES;
    while (lo < hi) {
        int mid = (lo + hi) >> 1;
        if (edge_row[mid] < i) lo = mid + 1;
        else hi = mid;
    }
    g_rowptr[i] = lo;
}

// ---------------------------------------------------------------------------
// Tensor-core GEMM via mma.sync (bf16 3-pass split):
//   out[m][n] = sum_k A[m][k] * W[n][k]
// BM=128, BK=32, 256 threads (8 warps).
// N=128: warp grid 2x4 (warp tile 64x32). N=64: 4x2 (warp tile 32x32).
// Smem tiles row-major with 40-element (80B) row stride: conflict-free ldmatrix.
// ---------------------------------------------------------------------------
template<int N, int K>
__global__ void __launch_bounds__(256) gemm_mma(const float* __restrict__ A,
                                                const float* __restrict__ W,
                                                float* __restrict__ out, int M) {
    constexpr int BM = 128;
    constexpr int LDSB = 40;                 // bf16 elems per smem row (80 bytes)
    constexpr int WCOLS = N / 32;            // warps along N
    constexpr int WROWS = 8 / WCOLS;         // warps along M
    constexpr int WTM = BM / WROWS;          // warp tile rows (64 or 32)
    constexpr int MT = WTM / 16;             // m16 tiles per warp (4 or 2)

    __shared__ __nv_bfloat16 sAh[BM * LDSB];
    __shared__ __nv_bfloat16 sAl[BM * LDSB];
    __shared__ __nv_bfloat16 sWh[N * LDSB];
    __shared__ __nv_bfloat16 sWl[N * LDSB];

    const int tid  = threadIdx.x;
    const int wid  = tid >> 5;
    const int lane = tid & 31;
    const int wm   = (wid / WCOLS) * WTM;    // warp row origin in tile
    const int wn   = (wid % WCOLS) * 32;     // warp col origin
    const int bm   = blockIdx.x * BM;
    const int arows = min(BM, M - bm);

    const uint32_t aH = smem_u32(sAh), aL = smem_u32(sAl);
    const uint32_t wH = smem_u32(sWh), wL = smem_u32(sWl);

    const int lrow  = lane & 15;             // ldmatrix row within 16-row tile
    const int lcolb = (lane >> 4) * 16;      // ldmatrix col byte offset (0/16)

    float acc[MT][4][4];
#pragma unroll
    for (int i = 0; i < MT; i++)
#pragma unroll
        for (int j = 0; j < 4; j++)
#pragma unroll
            for (int c = 0; c < 4; c++) acc[i][j][c] = 0.f;

    for (int k0 = 0; k0 < K; k0 += 32) {
        // Load + split A chunk [128 x 32]
#pragma unroll
        for (int idx = tid; idx < BM * 8; idx += 256) {
            int row = idx >> 3, g = idx & 7;
            float4 v = make_float4(0.f, 0.f, 0.f, 0.f);
            if (row < arows)
                v = *reinterpret_cast<const float4*>(&A[(size_t)(bm + row) * K + k0 + g * 4]);
            uint2 hv, lv;
            split4(v, hv, lv);
            *reinterpret_cast<uint2*>(&sAh[row * LDSB + g * 4]) = hv;
            *reinterpret_cast<uint2*>(&sAl[row * LDSB + g * 4]) = lv;
        }
        // Load + split W chunk [N x 32]
#pragma unroll
        for (int idx = tid; idx < N * 8; idx += 256) {
            int row = idx >> 3, g = idx & 7;
            float4 v = *reinterpret_cast<const float4*>(&W[(size_t)row * K + k0 + g * 4]);
            uint2 hv, lv;
            split4(v, hv, lv);
            *reinterpret_cast<uint2*>(&sWh[row * LDSB + g * 4]) = hv;
            *reinterpret_cast<uint2*>(&sWl[row * LDSB + g * 4]) = lv;
        }
        __syncthreads();

#pragma unroll
        for (int ks = 0; ks < 2; ks++) {
            const uint32_t cb = (uint32_t)(ks * 32 + lcolb);
            uint32_t afh[MT][4], afl[MT][4];
#pragma unroll
            for (int mt = 0; mt < MT; mt++) {
                uint32_t ro = (uint32_t)((wm + mt * 16 + lrow) * (LDSB * 2)) + cb;
                ldsm_x4(afh[mt], aH + ro);
                ldsm_x4(afl[mt], aL + ro);
            }
            uint32_t bfh[2][4], bfl[2][4];
#pragma unroll
            for (int np = 0; np < 2; np++) {
                uint32_t ro = (uint32_t)((wn + np * 16 + lrow) * (LDSB * 2)) + cb;
                ldsm_x4(bfh[np], wH + ro);
                ldsm_x4(bfl[np], wL + ro);
            }
#pragma unroll
            for (int mt = 0; mt < MT; mt++) {
#pragma unroll
                for (int nt = 0; nt < 4; nt++) {
                    int np = nt >> 1, h = nt & 1;
                    mma_bf16(acc[mt][nt], afh[mt], bfh[np][h], bfh[np][h + 2]); // hi*hi
                    mma_bf16(acc[mt][nt], afl[mt], bfh[np][h], bfh[np][h + 2]); // lo*hi
                    mma_bf16(acc[mt][nt], afh[mt], bfl[np][h], bfl[np][h + 2]); // hi*lo
                }
            }
        }
        __syncthreads();
    }

    // Epilogue: mma d-frag layout -> global
#pragma unroll
    for (int mt = 0; mt < MT; mt++) {
#pragma unroll
        for (int nt = 0; nt < 4; nt++) {
            int r0 = wm + mt * 16 + (lane >> 2);
            int c0 = wn + nt * 8 + (lane & 3) * 2;
            if (r0 < arows)
                *reinterpret_cast<float2*>(&out[(size_t)(bm + r0) * N + c0]) =
                    make_float2(acc[mt][nt][0], acc[mt][nt][1]);
            if (r0 + 8 < arows)
                *reinterpret_cast<float2*>(&out[(size_t)(bm + r0 + 8) * N + c0]) =
                    make_float2(acc[mt][nt][2], acc[mt][nt][3]);
        }
    }
}

// ---------------------------------------------------------------------------
// SpMM (H=128): one warp per row, float4 per lane, optional ReLU
// ---------------------------------------------------------------------------
template<bool RELU>
__global__ void __launch_bounds__(256) spmm128_kernel(const int* __restrict__ edge_col,
                                                      const float* __restrict__ edge_val,
                                                      const float* __restrict__ Z,
                                                      float* __restrict__ out) {
    int gw   = (blockIdx.x * blockDim.x + threadIdx.x) >> 5;
    int lane = threadIdx.x & 31;
    if (gw >= N_NODES) return;
    int s = g_rowptr[gw];
    int e = g_rowptr[gw + 1];

    float4 acc = make_float4(0.f, 0.f, 0.f, 0.f);
    for (int i = s; i < e; i++) {
        int   col = __ldg(&edge_col[i]);
        float val = __ldg(&edge_val[i]);
        float4 z = *reinterpret_cast<const float4*>(&Z[(size_t)col * H_DIM + lane * 4]);
        acc.x = fmaf(val, z.x, acc.x);
        acc.y = fmaf(val, z.y, acc.y);
        acc.z = fmaf(val, z.z, acc.z);
        acc.w = fmaf(val, z.w, acc.w);
    }
    if (RELU) {
        acc.x = fmaxf(acc.x, 0.f);
        acc.y = fmaxf(acc.y, 0.f);
        acc.z = fmaxf(acc.z, 0.f);
        acc.w = fmaxf(acc.w, 0.f);
    }
    *reinterpret_cast<float4*>(&out[(size_t)gw * H_DIM + lane * 4]) = acc;
}

// ---------------------------------------------------------------------------
// Final SpMM (F=64) fused with row softmax
// ---------------------------------------------------------------------------
__global__ void __launch_bounds__(256) spmm64_softmax_kernel(const int* __restrict__ edge_col,
                                                             const float* __restrict__ edge_val,
                                                             const float* __restrict__ Z,
                                                             float* __restrict__ out) {
    int gw   = (blockIdx.x * blockDim.x + threadIdx.x) >> 5;
    int lane = threadIdx.x & 31;
    if (gw >= N_NODES) return;
    int s = g_rowptr[gw];
    int e = g_rowptr[gw + 1];

    float a0 = 0.f, a1 = 0.f;
    for (int i = s; i < e; i++) {
        int   col = __ldg(&edge_col[i]);
        float val = __ldg(&edge_val[i]);
        float2 z = *reinterpret_cast<const float2*>(&Z[(size_t)col * F_DIM + lane * 2]);
        a0 = fmaf(val, z.x, a0);
        a1 = fmaf(val, z.y, a1);
    }
    float m = fmaxf(a0, a1);
#pragma unroll
    for (int off = 16; off > 0; off >>= 1)
        m = fmaxf(m, __shfl_xor_sync(0xFFFFFFFFu, m, off));
    float e0 = expf(a0 - m);
    float e1 = expf(a1 - m);
    float ssum = e0 + e1;
#pragma unroll
    for (int off = 16; off > 0; off >>= 1)
        ssum += __shfl_xor_sync(0xFFFFFFFFu, ssum, off);
    float inv = 1.0f / ssum;
    float2 r = make_float2(e0 * inv, e1 * inv);
    *reinterpret_cast<float2*>(&out[(size_t)gw * F_DIM + lane * 2]) = r;
}

// ---------------------------------------------------------------------------
// Launch
// ---------------------------------------------------------------------------
extern "C" void kernel_launch(void* const* d_in, const int* in_sizes, int n_in,
                              void* d_out, int out_size) {
    const float* X        = (const float*)d_in[0];
    const int*   edge_row = (const int*)d_in[1];
    const int*   edge_col = (const int*)d_in[2];
    const float* edge_val = (const float*)d_in[3];
    const float* W0       = (const float*)d_in[4];
    const float* Wh0      = (const float*)d_in[5];
    const float* W1       = (const float*)d_in[6];
    float*       out      = (float*)d_out;

    float *buf1, *buf2;
    cudaGetSymbolAddress((void**)&buf1, g_buf1);
    cudaGetSymbolAddress((void**)&buf2, g_buf2);

    const int gemm_grid = (N_NODES + 127) / 128;               // 782
    const int spmm_grid = (N_NODES * 32 + 255) / 256;          // 12500

    rowptr_kernel<<<(N_NODES + 1 + 255) / 256, 256>>>(edge_row);

    // Layer 0: buf1 = X @ W0^T ; buf2 = relu(A @ buf1)
    gemm_mma<128, 256><<<gemm_grid, 256>>>(X, W0, buf1, N_NODES);
    spmm128_kernel<true><<<spmm_grid, 256>>>(edge_col, edge_val, buf1, buf2);

    // Hidden: buf1 = buf2 @ Wh0^T ; buf2 = relu(A @ buf1)
    gemm_mma<128, 128><<<gemm_grid, 256>>>(buf2, Wh0, buf1, N_NODES);
    spmm128_kernel<true><<<spmm_grid, 256>>>(edge_col, edge_val, buf1, buf2);

    // Output: buf1 = buf2 @ W1^T ; out = softmax(A @ buf1)
    gemm_mma<64, 128><<<gemm_grid, 256>>>(buf2, W1, buf1, N_NODES);
    spmm64_softmax_kernel<<<spmm_grid, 256>>>(edge_col, edge_val, buf1, out);
}